// round 7
// baseline (speedup 1.0000x reference)
#include <cuda_runtime.h>

#define BB 512
#define SS 512
#define EE 64
#define BOSs 1
#define EOSs 2
#define NE 8   // normalize every 8 steps (deferred apply)

typedef unsigned long long u64;

// Scratch (device globals — allocation-free rule)
__device__ float g_val[BB];
__device__ unsigned int g_ctr = 0;

// ---- packed fp32x2 helpers (sm_103a FFMA2, PTX-only) ----
__device__ __forceinline__ u64 ffma2(u64 a, u64 b, u64 c) {
    u64 d;
    asm("fma.rn.f32x2 %0, %1, %2, %3;" : "=l"(d) : "l"(a), "l"(b), "l"(c));
    return d;
}
__device__ __forceinline__ u64 fadd2(u64 a, u64 b) {
    u64 d;
    asm("add.rn.f32x2 %0, %1, %2;" : "=l"(d) : "l"(a), "l"(b));
    return d;
}
__device__ __forceinline__ u64 pack2(float lo, float hi) {
    u64 d;
    asm("mov.b64 %0, {%1, %2};" : "=l"(d) : "f"(lo), "f"(hi));
    return d;
}
__device__ __forceinline__ float2 unpack2(u64 v) {
    float lo, hi;
    asm("mov.b64 {%0, %1}, %2;" : "=f"(lo), "=f"(hi) : "l"(v));
    float2 r; r.x = lo; r.y = hi; return r;
}

// ---------------------------------------------------------------------------
// Fused forward + score: ONE WARP per sequence. Thread owns states
// (2*lane, 2*lane+1); exp(T) column pairs in registers; alpha exchanged via
// smem with __syncwarp only (no block barrier). Deferred rescale every NE.
// ---------------------------------------------------------------------------
__global__ __launch_bounds__(32) void crf_fused(
    const float* __restrict__ em,     // [B,S,E]
    const float* __restrict__ T,      // [E,E]
    const int*   __restrict__ ent,    // [B,S]
    const int*   __restrict__ mask,   // [B,S] (bool as int32)
    float* __restrict__ out)
{
    __shared__ __align__(16) float abuf[2][EE];
    __shared__ __align__(16) float Tsh[EE * EE];
    __shared__ __align__(16) int   esh[SS];
    __shared__ __align__(16) int   msh[SS];

    const int b    = blockIdx.x;
    const int lane = threadIdx.x;
    const int j0   = 2 * lane;
    const int j1   = 2 * lane + 1;

    // Stage T, entities, mask (coalesced vector loads, one warp).
    {
        const float4* Tg = reinterpret_cast<const float4*>(T);
        float4*       Ts = reinterpret_cast<float4*>(Tsh);
#pragma unroll
        for (int i = lane; i < EE * EE / 4; i += 32) Ts[i] = Tg[i];
        const int4* eg = reinterpret_cast<const int4*>(ent + (size_t)b * SS);
        const int4* mg = reinterpret_cast<const int4*>(mask + (size_t)b * SS);
        int4* es = reinterpret_cast<int4*>(esh);
        int4* ms = reinterpret_cast<int4*>(msh);
#pragma unroll
        for (int i = lane; i < SS / 4; i += 32) { es[i] = eg[i]; ms[i] = mg[i]; }
    }
    __syncwarp();

    // Packed M columns for this thread's two states.
    // exp(-10000) underflows to exactly 0 — matches logsumexp semantics.
    u64 mp0[EE / 2], mp1[EE / 2];
#pragma unroll
    for (int k = 0; k < EE / 2; k++) {
        mp0[k] = pack2(__expf(Tsh[(2 * k) * EE + j0]), __expf(Tsh[(2 * k + 1) * EE + j0]));
        mp1[k] = pack2(__expf(Tsh[(2 * k) * EE + j1]), __expf(Tsh[(2 * k + 1) * EE + j1]));
    }

    const float*  emb = em + (size_t)b * SS * EE;
    const float2* em2 = reinterpret_cast<const float2*>(emb);

    // t = 0: raw alpha; sum published for deferred scale at t=1.
    float2 emc = em2[lane];
    float a0 = __expf(Tsh[BOSs * EE + j0] + emc.x);
    float a1 = __expf(Tsh[BOSs * EE + j1] + emc.y);
    float logC = 0.f;
    float s = a0 + a1;
#pragma unroll
    for (int o = 16; o > 0; o >>= 1) s += __shfl_xor_sync(0xffffffffu, s, o);
    reinterpret_cast<float2*>(abuf[0])[lane] = make_float2(a0, a1);
    __syncwarp();

    float accS  = 0.f;
    int   ep    = esh[0];
    int   lastE = ep;
    int   cur   = 0;
    float2 emn  = em2[32 + lane];   // prefetch t=1

    for (int t = 1; t < SS; t++) {
        const float2 emv = emn;
        if (t + 1 < SS) emn = em2[(t + 1) * 32 + lane];
        const float ex0 = __expf(emv.x);     // off the critical tail
        const float ex1 = __expf(emv.y);
        const int m = msh[t];
        const int e = esh[t];

        // Two dot products over i (packed pairs), shared LDS.128 stream.
        const ulonglong2* av = reinterpret_cast<const ulonglong2*>(abuf[cur]);
        u64 A0 = 0ull, A1 = 0ull, A2 = 0ull, A3 = 0ull;
        u64 B0 = 0ull, B1 = 0ull, B2 = 0ull, B3 = 0ull;
#pragma unroll
        for (int k = 0; k < 16; k += 2) {
            const ulonglong2 p = av[k];
            const ulonglong2 q = av[k + 1];
            A0 = ffma2(p.x, mp0[2 * k + 0], A0);
            A1 = ffma2(p.y, mp0[2 * k + 1], A1);
            B0 = ffma2(p.x, mp1[2 * k + 0], B0);
            B1 = ffma2(p.y, mp1[2 * k + 1], B1);
            A2 = ffma2(q.x, mp0[2 * k + 2], A2);
            A3 = ffma2(q.y, mp0[2 * k + 3], A3);
            B2 = ffma2(q.x, mp1[2 * k + 2], B2);
            B3 = ffma2(q.y, mp1[2 * k + 3], B3);
        }
        const float2 va = unpack2(fadd2(fadd2(A0, A1), fadd2(A2, A3)));
        const float2 vb = unpack2(fadd2(fadd2(B0, B1), fadd2(B2, B3)));
        float v0 = (va.x + va.y) * ex0;
        float v1 = (vb.x + vb.y) * ex1;

        // Deferred scale: first step after a norm step applies 1/S.
        if ((t & (NE - 1)) == 1) {
            const float invS = 1.0f / s;
            logC += __logf(s);
            v0 *= invS; v1 *= invS;
            a0 = m ? v0 : a0 * invS;
            a1 = m ? v1 : a1 * invS;
        } else {
            a0 = m ? v0 : a0;
            a1 = m ? v1 : a1;
        }

        // Fused path score.
        if (m) {
            if ((e >> 1) == lane)
                accS += ((e & 1) ? emv.y : emv.x) + Tsh[ep * EE + e];
            lastE = e;
        }
        ep = e;

        // Norm step: warp-local sum, consumed at t+1 (chain hides under FMAs).
        if ((t & (NE - 1)) == 0) {
            s = a0 + a1;
#pragma unroll
            for (int o = 16; o > 0; o >>= 1) s += __shfl_xor_sync(0xffffffffu, s, o);
        }

        reinterpret_cast<float2*>(abuf[cur ^ 1])[lane] = make_float2(a0, a1);
        __syncwarp();
        cur ^= 1;
    }

    // Finish: z = sum_j a_j * exp(T[j,EOS]); reduce z and score together.
    float z  = a0 * __expf(Tsh[j0 * EE + EOSs]) + a1 * __expf(Tsh[j1 * EE + EOSs]);
    float sc = accS;
#pragma unroll
    for (int o = 16; o > 0; o >>= 1) {
        z  += __shfl_xor_sync(0xffffffffu, z, o);
        sc += __shfl_xor_sync(0xffffffffu, sc, o);
    }
    if (lane == 0) {
        const int e0 = esh[0];
        const float score = sc + Tsh[BOSs * EE + e0] + emb[e0] + Tsh[lastE * EE + EOSs];
        g_val[b] = (logC + __logf(z)) - score;
    }

    // Last block to arrive performs the mean-reduce (fixed order → deterministic).
    __threadfence();
    unsigned int tk = 0;
    if (lane == 0) tk = atomicAdd(&g_ctr, 1u);
    tk = __shfl_sync(0xffffffffu, tk, 0);
    if (tk == BB - 1) {
        __threadfence();
        float acc = 0.f;
#pragma unroll
        for (int i = 0; i < BB / 32; i++) acc += __ldcg(&g_val[i * 32 + lane]);
#pragma unroll
        for (int o = 16; o > 0; o >>= 1) acc += __shfl_xor_sync(0xffffffffu, acc, o);
        if (lane == 0) {
            out[0] = acc / (float)BB;
            g_ctr = 0;   // reset for next graph replay
        }
    }
}

extern "C" void kernel_launch(void* const* d_in, const int* in_sizes, int n_in,
                              void* d_out, int out_size) {
    const float* emissions   = (const float*)d_in[0];
    const float* transitions = (const float*)d_in[1];
    const int*   entities    = (const int*)d_in[2];
    const int*   mask        = (const int*)d_in[3];
    float* out               = (float*)d_out;

    crf_fused<<<BB, 32>>>(emissions, transitions, entities, mask, out);
}

// round 9
// speedup vs baseline: 1.0870x; 1.0870x over previous
#include <cuda_runtime.h>

#define BB 512
#define SS 512
#define EE 64
#define BOSs 1
#define EOSs 2
#define NE 8   // normalize every 8 steps (deferred apply)

typedef unsigned long long u64;

// Scratch (device globals — allocation-free rule)
__device__ float g_val[BB];
__device__ unsigned int g_ctr = 0;

// ---- packed fp32x2 helpers (sm_103a FFMA2, PTX-only) ----
__device__ __forceinline__ u64 ffma2(u64 a, u64 b, u64 c) {
    u64 d;
    asm("fma.rn.f32x2 %0, %1, %2, %3;" : "=l"(d) : "l"(a), "l"(b), "l"(c));
    return d;
}
__device__ __forceinline__ u64 fadd2(u64 a, u64 b) {
    u64 d;
    asm("add.rn.f32x2 %0, %1, %2;" : "=l"(d) : "l"(a), "l"(b));
    return d;
}
__device__ __forceinline__ u64 pack2(float lo, float hi) {
    u64 d;
    asm("mov.b64 %0, {%1, %2};" : "=l"(d) : "f"(lo), "f"(hi));
    return d;
}
__device__ __forceinline__ float2 unpack2(u64 v) {
    float lo, hi;
    asm("mov.b64 {%0, %1}, %2;" : "=f"(lo), "=f"(hi) : "l"(v));
    float2 r; r.x = lo; r.y = hi; return r;
}

// ---------------------------------------------------------------------------
// Fused forward + score: 128 threads per sequence.
// Thread (half, j) computes the partial dot for state j over half the i-range
// (16 FFMA2 each); halves combine via smem. 2 barriers/step, but 3.46
// warps/SMSP chip-wide hide the latency (R5/R7 comparison: occupancy is the
// binding constraint, not fma throughput).
// ---------------------------------------------------------------------------
__global__ __launch_bounds__(128) void crf_fused(
    const float* __restrict__ em,     // [B,S,E]
    const float* __restrict__ T,      // [E,E]
    const int*   __restrict__ ent,    // [B,S]
    const int*   __restrict__ mask,   // [B,S] (bool as int32)
    float* __restrict__ out)
{
    __shared__ __align__(16) float abuf[2][EE];
    __shared__ __align__(8)  float pbuf[EE][2];
    __shared__ float red[4];          // per-warp alpha-sum partials (deferred)
    __shared__ float redz[4];         // final z partials
    __shared__ float reds[2];         // score partials
    __shared__ __align__(16) float Tsh[EE * EE];
    __shared__ __align__(16) int   esh[SS];
    __shared__ __align__(16) int   msh[SS];

    const int b    = blockIdx.x;
    const int tid  = threadIdx.x;
    const int j    = tid & 63;        // state
    const int half = tid >> 6;        // which half of the i-range
    const int lane = tid & 31;
    const int warp = tid >> 5;

    // Stage T, entities, mask (coalesced vector loads).
    {
        const float4* Tg = reinterpret_cast<const float4*>(T);
        float4*       Ts = reinterpret_cast<float4*>(Tsh);
#pragma unroll
        for (int i = tid; i < EE * EE / 4; i += 128) Ts[i] = Tg[i];
        const int4* eg = reinterpret_cast<const int4*>(ent + (size_t)b * SS);
        const int4* mg = reinterpret_cast<const int4*>(mask + (size_t)b * SS);
        int4* es = reinterpret_cast<int4*>(esh);
        int4* ms = reinterpret_cast<int4*>(msh);
#pragma unroll
        for (int i = tid; i < SS / 4; i += 128) { es[i] = eg[i]; ms[i] = mg[i]; }
    }
    __syncthreads();

    // Packed M sub-column for (half, j): 16 pairs over i in [32*half, 32*half+32).
    // exp(-10000) underflows to exactly 0 — matches logsumexp semantics.
    const int ilo = half * 32;
    u64 mp[16];
#pragma unroll
    for (int k = 0; k < 16; k++)
        mp[k] = pack2(__expf(Tsh[(ilo + 2 * k) * EE + j]),
                      __expf(Tsh[(ilo + 2 * k + 1) * EE + j]));

    const float* emb = em + (size_t)b * SS * EE;

    // t = 0: raw alpha; warp-partial sums published for deferred scale at t=1.
    float a    = __expf(Tsh[BOSs * EE + j] + emb[j]);
    float logC = 0.f;
    {
        float sw = a;
#pragma unroll
        for (int o = 16; o > 0; o >>= 1) sw += __shfl_xor_sync(0xffffffffu, sw, o);
        if (lane == 0) red[warp] = sw;
        if (half == 0) abuf[0][j] = a;
    }
    __syncthreads();

    float accS  = 0.f;
    int   ep    = esh[0];
    int   lastE = ep;
    int   cur   = 0;
    float emn   = emb[EE + j];   // prefetch t=1
    float s     = 0.f;

    for (int t = 1; t < SS; t++) {
        const float emv = emn;
        if (t + 1 < SS) emn = emb[(size_t)(t + 1) * EE + j];
        const float ex = __expf(emv);          // MUFU early, off the tail
        const int m = msh[t];
        const int e = esh[t];
        if ((t & (NE - 1)) == 1) s = red[0] + red[1];

        // Phase A: partial dot over this half's 32 i-values (16 FFMA2).
        const ulonglong2* av =
            reinterpret_cast<const ulonglong2*>(abuf[cur] + ilo);
        u64 A0 = 0ull, A1 = 0ull, A2 = 0ull, A3 = 0ull;
#pragma unroll
        for (int k = 0; k < 8; k += 2) {
            const ulonglong2 p = av[k];
            const ulonglong2 q = av[k + 1];
            A0 = ffma2(p.x, mp[2 * k + 0], A0);
            A1 = ffma2(p.y, mp[2 * k + 1], A1);
            A2 = ffma2(q.x, mp[2 * k + 2], A2);
            A3 = ffma2(q.y, mp[2 * k + 3], A3);
        }
        const float2 pa = unpack2(fadd2(fadd2(A0, A1), fadd2(A2, A3)));
        pbuf[j][half] = pa.x + pa.y;
        __syncthreads();   // bar A: partials visible

        // Phase B: combine halves, emission multiply, mask, scale, score.
        const float2 pp = *reinterpret_cast<const float2*>(&pbuf[j][0]);
        float v = (pp.x + pp.y) * ex;

        if ((t & (NE - 1)) == 1) {           // deferred scale apply
            const float invS = 1.0f / s;
            logC += __logf(s);
            v *= invS;
            a = m ? v : a * invS;
        } else {
            a = m ? v : a;
        }

        if (m) {
            if (half == 0 && j == e) accS += emv + Tsh[ep * EE + e];
            lastE = e;
        }
        ep = e;

        if ((t & (NE - 1)) == 0) {           // publish warp-partial sums
            float sw = a;
#pragma unroll
            for (int o = 16; o > 0; o >>= 1) sw += __shfl_xor_sync(0xffffffffu, sw, o);
            if (lane == 0) red[warp] = sw;
        }

        if (half == 0) abuf[cur ^ 1][j] = a;
        __syncthreads();   // bar B: new alpha visible
        cur ^= 1;
    }

    // Finish: z = sum_j a_j * exp(T[j,EOS]); combine z and score partials.
    {
        float z  = a * __expf(Tsh[j * EE + EOSs]);
        float sc = accS;
#pragma unroll
        for (int o = 16; o > 0; o >>= 1) {
            z  += __shfl_xor_sync(0xffffffffu, z, o);
            sc += __shfl_xor_sync(0xffffffffu, sc, o);
        }
        if (lane == 0) {
            redz[warp] = z;
            if (warp < 2) reds[warp] = sc;
        }
        __syncthreads();
        if (tid == 0) {
            const int e0 = esh[0];
            const float score = reds[0] + reds[1]
                              + Tsh[BOSs * EE + e0] + emb[e0]
                              + Tsh[lastE * EE + EOSs];
            g_val[b] = (logC + __logf(redz[0] + redz[1])) - score;
        }
    }

    // Last block to arrive does the mean-reduce (fixed order → deterministic).
    __threadfence();
    if (warp == 0) {
        unsigned int tk = 0;
        if (lane == 0) tk = atomicAdd(&g_ctr, 1u);
        tk = __shfl_sync(0xffffffffu, tk, 0);
        if (tk == BB - 1) {
            __threadfence();
            float acc = 0.f;
#pragma unroll
            for (int i = 0; i < BB / 32; i++) acc += __ldcg(&g_val[i * 32 + lane]);
#pragma unroll
            for (int o = 16; o > 0; o >>= 1) acc += __shfl_xor_sync(0xffffffffu, acc, o);
            if (lane == 0) {
                out[0] = acc / (float)BB;
                g_ctr = 0;   // reset for next graph replay
            }
        }
    }
}

extern "C" void kernel_launch(void* const* d_in, const int* in_sizes, int n_in,
                              void* d_out, int out_size) {
    const float* emissions   = (const float*)d_in[0];
    const float* transitions = (const float*)d_in[1];
    const int*   entities    = (const int*)d_in[2];
    const int*   mask        = (const int*)d_in[3];
    float* out               = (float*)d_out;

    crf_fused<<<BB, 128>>>(emissions, transitions, entities, mask, out);
}